// round 9
// baseline (speedup 1.0000x reference)
#include <cuda_runtime.h>
#include <cuda_bf16.h>
#include <cstdint>

// ---------------------------------------------------------------------------
// HyperbolicGraphPooling: out[g] = sum_{n: batch[n]==g} sigmoid(f[n]·W+b) * f[n]
// N=500000, C=256, 2048 graphs, batch int32 sorted ascending.
// R9: dynamic scheduling retry with CHUNK=8 (R8's CHUNK=32 gave 2.6 chunks/
// warp -> 1.5x imbalance). cp.async pipeline + commit-group stream flows
// CONTINUOUSLY across chunk boundaries (no re-prime bubble); next chunk id
// grabbed one chunk ahead so ATOMG latency is hidden. Target ~80-84 us.
// ---------------------------------------------------------------------------

#define CHANNELS 256
#define THREADS  256
#define WARPS    (THREADS / 32)
#define STAGES   4
#define CHUNK    8

__device__ unsigned int g_chunk_counter;

__global__ void hgp_zero_kernel(float4* __restrict__ out, int n4) {
    int i = blockIdx.x * blockDim.x + threadIdx.x;
    if (i == 0) g_chunk_counter = 0u;           // reset work queue each replay
    if (i < n4) out[i] = make_float4(0.f, 0.f, 0.f, 0.f);
}

__device__ __forceinline__ void flush_seg(float* __restrict__ out,
                                          int seg, int num_segs, int lane,
                                          const float4& a0, const float4& a1) {
    if (seg < 0 || seg >= num_segs) return;   // defensive
    float* p0 = out + (size_t)seg * CHANNELS + 4 * lane;
    float* p1 = p0 + 128;
    atomicAdd(p0 + 0, a0.x);
    atomicAdd(p0 + 1, a0.y);
    atomicAdd(p0 + 2, a0.z);
    atomicAdd(p0 + 3, a0.w);
    atomicAdd(p1 + 0, a1.x);
    atomicAdd(p1 + 1, a1.y);
    atomicAdd(p1 + 2, a1.z);
    atomicAdd(p1 + 3, a1.w);
}

__device__ __forceinline__ void cp_row(unsigned int s_dst,
                                       const float* __restrict__ feat,
                                       int row, int lane) {
    // Each lane copies its own 32B: channels [4*lane,4*lane+4) and +128.
    const char* g = reinterpret_cast<const char*>(feat + (size_t)row * CHANNELS)
                    + lane * 16;
    asm volatile("cp.async.cg.shared.global [%0], [%1], 16;\n"
                 "cp.async.cg.shared.global [%2], [%3], 16;"
                 :: "r"(s_dst + lane * 16), "l"(g),
                    "r"(s_dst + 512 + lane * 16), "l"(g + 512));
}

__device__ __forceinline__ unsigned int grab_chunk(int lane) {
    unsigned int c = 0;
    if (lane == 0) c = atomicAdd(&g_chunk_counter, 1u);
    return __shfl_sync(0xFFFFFFFFu, c, 0);
}

__global__ __launch_bounds__(THREADS, 5)
void hgp_pool_kernel(const float* __restrict__ feat,
                     const int* __restrict__ batch,
                     const float* __restrict__ W,
                     const float* __restrict__ b,
                     float* __restrict__ out,
                     int N, int num_segs) {
    __shared__ __align__(16) float ring[WARPS][STAGES][CHANNELS];

    const int lane = threadIdx.x & 31;
    const int wid  = threadIdx.x >> 5;

    const unsigned int s_base =
        (unsigned int)__cvta_generic_to_shared(&ring[wid][0][0]);

    const float4 w0 = *reinterpret_cast<const float4*>(W + 4 * lane);
    const float4 w1 = *reinterpret_cast<const float4*>(W + 128 + 4 * lane);
    const float bias = b[0];

    // Grab first two chunks (grab-ahead by one).
    unsigned int c_cur  = grab_chunk(lane);
    unsigned int c_next = grab_chunk(lane);
    int base = (int)(c_cur * CHUNK);
    if (base >= N) return;

    // Prologue: issue stream positions 0..2 = rows base..base+2 (clamped).
    unsigned int sp = 0;   // per-warp stream position (slot = sp & 3)
    #pragma unroll
    for (int p = 0; p < STAGES - 1; ++p) {
        int pr = base + p;
        if (pr >= N) pr = N - 1;
        cp_row(s_base + (((unsigned)p & (STAGES - 1)) << 10), feat, pr, lane);
        asm volatile("cp.async.commit_group;" ::: "memory");
    }

    while (base < N) {
        const long long nbase = (long long)c_next * CHUNK;   // may exceed N
        const int n1 = (base + CHUNK < N) ? base + CHUNK : N;

        float4 a0 = make_float4(0.f, 0.f, 0.f, 0.f);
        float4 a1 = make_float4(0.f, 0.f, 0.f, 0.f);
        int cur = __ldg(batch + base);

        for (int i = 0; base + i < n1; ++i) {
            // Prefetch stream position sp+3: row in this chunk or the next.
            {
                const int t = i + (STAGES - 1);
                long long prow = (t < CHUNK) ? (long long)(base + t)
                                             : nbase + (t - CHUNK);
                if (prow >= N) prow = N - 1;
                cp_row(s_base + (((sp + STAGES - 1) & (STAGES - 1)) << 10),
                       feat, (int)prow, lane);
                asm volatile("cp.async.commit_group;" ::: "memory");
            }

            const int g = __ldg(batch + base + i);

            // Position sp's group is 4th most recent -> wait_group 3.
            asm volatile("cp.async.wait_group 3;" ::: "memory");

            const float* srow = &ring[wid][sp & (STAGES - 1)][0];
            const float4 f0 = *reinterpret_cast<const float4*>(srow + 4 * lane);
            const float4 f1 = *reinterpret_cast<const float4*>(srow + 128 + 4 * lane);
            ++sp;

            if (g != cur) {
                flush_seg(out, cur, num_segs, lane, a0, a1);
                a0 = make_float4(0.f, 0.f, 0.f, 0.f);
                a1 = make_float4(0.f, 0.f, 0.f, 0.f);
                cur = g;
            }

            float s = f0.x * w0.x + f0.y * w0.y + f0.z * w0.z + f0.w * w0.w
                    + f1.x * w1.x + f1.y * w1.y + f1.z * w1.z + f1.w * w1.w;
            #pragma unroll
            for (int o = 16; o > 0; o >>= 1)
                s += __shfl_xor_sync(0xFFFFFFFFu, s, o);

            const float wgt = __fdividef(1.0f, 1.0f + __expf(-(s + bias)));

            a0.x += f0.x * wgt; a0.y += f0.y * wgt;
            a0.z += f0.z * wgt; a0.w += f0.w * wgt;
            a1.x += f1.x * wgt; a1.y += f1.y * wgt;
            a1.z += f1.z * wgt; a1.w += f1.w * wgt;
        }

        flush_seg(out, cur, num_segs, lane, a0, a1);

        // Rotate to next chunk; grab a new one (latency hidden behind the
        // next ~5 nodes of work before it is first needed for prefetch).
        base   = (nbase < (long long)N) ? (int)nbase : N;
        c_next = grab_chunk(lane);
    }
}

extern "C" void kernel_launch(void* const* d_in, const int* in_sizes, int n_in,
                              void* d_out, int out_size) {
    const float* feat  = (const float*)d_in[0];  // [N, 256] f32
    const int*   batch = (const int*)d_in[1];    // [N] i32, sorted
    const float* W     = (const float*)d_in[2];  // [256, 1] f32
    const float* b     = (const float*)d_in[3];  // [1] f32
    float*       out   = (float*)d_out;          // [num_segs, 256] f32

    const int N        = in_sizes[1];
    const int num_segs = out_size / CHANNELS;    // 2048

    const int n4 = out_size / 4;
    hgp_zero_kernel<<<(n4 + THREADS - 1) / THREADS, THREADS>>>(
        (float4*)out, n4);

    // 148 SMs * 5 blocks * 8 warps = 5920 warps pulling 8-node chunks.
    const int blocks = 740;
    hgp_pool_kernel<<<blocks, THREADS>>>(feat, batch, W, b, out, N, num_segs);
}

// round 10
// speedup vs baseline: 1.4440x; 1.4440x over previous
#include <cuda_runtime.h>
#include <cuda_bf16.h>
#include <cstdint>

// ---------------------------------------------------------------------------
// HyperbolicGraphPooling: out[g] = sum_{n: batch[n]==g} sigmoid(f[n]·W+b) * f[n]
// N=500000, C=256, 2048 graphs, batch int32 sorted ascending.
// R10: STATIC INTERLEAVED chunks (CHUNK=8, stride = total warps) - zero
// atomics (R9's single-counter ATOMG serialized the chip: 172us). Every warp
// samples the same near/far-L2-die address mix -> per-warp service rates
// equalize, compressing the R7 tail (DRAM idle 23%). cp.async ring streams
// continuously across chunk boundaries. Target ~82-85 us.
// ---------------------------------------------------------------------------

#define CHANNELS 256
#define THREADS  256
#define WARPS    (THREADS / 32)
#define STAGES   4
#define CHUNK    8

__global__ void hgp_zero_kernel(float4* __restrict__ out, int n4) {
    int i = blockIdx.x * blockDim.x + threadIdx.x;
    if (i < n4) out[i] = make_float4(0.f, 0.f, 0.f, 0.f);
}

__device__ __forceinline__ void flush_seg(float* __restrict__ out,
                                          int seg, int num_segs, int lane,
                                          const float4& a0, const float4& a1) {
    if (seg < 0 || seg >= num_segs) return;   // defensive
    float* p0 = out + (size_t)seg * CHANNELS + 4 * lane;
    float* p1 = p0 + 128;
    atomicAdd(p0 + 0, a0.x);
    atomicAdd(p0 + 1, a0.y);
    atomicAdd(p0 + 2, a0.z);
    atomicAdd(p0 + 3, a0.w);
    atomicAdd(p1 + 0, a1.x);
    atomicAdd(p1 + 1, a1.y);
    atomicAdd(p1 + 2, a1.z);
    atomicAdd(p1 + 3, a1.w);
}

__device__ __forceinline__ void cp_row(unsigned int s_dst,
                                       const float* __restrict__ feat,
                                       int row, int lane) {
    // Each lane copies its own 32B: channels [4*lane,4*lane+4) and +128.
    const char* g = reinterpret_cast<const char*>(feat + (size_t)row * CHANNELS)
                    + lane * 16;
    asm volatile("cp.async.cg.shared.global [%0], [%1], 16;\n"
                 "cp.async.cg.shared.global [%2], [%3], 16;"
                 :: "r"(s_dst + lane * 16), "l"(g),
                    "r"(s_dst + 512 + lane * 16), "l"(g + 512));
}

__global__ __launch_bounds__(THREADS, 5)
void hgp_pool_kernel(const float* __restrict__ feat,
                     const int* __restrict__ batch,
                     const float* __restrict__ W,
                     const float* __restrict__ b,
                     float* __restrict__ out,
                     int N, int num_segs) {
    __shared__ __align__(16) float ring[WARPS][STAGES][CHANNELS];

    const int lane        = threadIdx.x & 31;
    const int wid         = threadIdx.x >> 5;
    const int warp_global = (blockIdx.x * blockDim.x + threadIdx.x) >> 5;
    const int total_warps = (gridDim.x * blockDim.x) >> 5;
    const int stride      = total_warps * CHUNK;   // node stride between chunks

    const unsigned int s_base =
        (unsigned int)__cvta_generic_to_shared(&ring[wid][0][0]);

    const float4 w0 = *reinterpret_cast<const float4*>(W + 4 * lane);
    const float4 w1 = *reinterpret_cast<const float4*>(W + 128 + 4 * lane);
    const float bias = b[0];

    int cbase = warp_global * CHUNK;       // first chunk base (< N always)
    if (cbase >= N) return;

    // Prologue: stream positions 0..2 = rows cbase..cbase+2 (CHUNK>=4, full
    // chunks since N % CHUNK == 0; clamp anyway for safety).
    #pragma unroll
    for (int p = 0; p < STAGES - 1; ++p) {
        int pr = cbase + p;
        if (pr >= N) pr = N - 1;
        cp_row(s_base + ((unsigned)p << 10), feat, pr, lane);
        asm volatile("cp.async.commit_group;" ::: "memory");
    }

    while (cbase < N) {
        const int nbase = cbase + stride;            // next chunk base
        const int n1    = (cbase + CHUNK < N) ? cbase + CHUNK : N;

        float4 a0 = make_float4(0.f, 0.f, 0.f, 0.f);
        float4 a1 = make_float4(0.f, 0.f, 0.f, 0.f);
        int cur = __ldg(batch + cbase);

        // CHUNK % STAGES == 0, so stream position == i (mod 4) every chunk.
        #pragma unroll
        for (int i = 0; i < CHUNK; ++i) {
            const int n = cbase + i;
            if (n >= n1) break;

            // Prefetch stream position i+3: this chunk or the next one.
            {
                const int t = i + (STAGES - 1);
                int prow = (t < CHUNK) ? cbase + t : nbase + (t - CHUNK);
                if (prow >= N) prow = N - 1;
                cp_row(s_base + (((unsigned)(t & (STAGES - 1))) << 10),
                       feat, prow, lane);
                asm volatile("cp.async.commit_group;" ::: "memory");
            }

            const int g = __ldg(batch + n);

            // Position i's group is 4th most recent -> wait_group 3.
            asm volatile("cp.async.wait_group 3;" ::: "memory");

            const float* srow = &ring[wid][i & (STAGES - 1)][0];
            const float4 f0 = *reinterpret_cast<const float4*>(srow + 4 * lane);
            const float4 f1 = *reinterpret_cast<const float4*>(srow + 128 + 4 * lane);

            if (g != cur) {
                flush_seg(out, cur, num_segs, lane, a0, a1);
                a0 = make_float4(0.f, 0.f, 0.f, 0.f);
                a1 = make_float4(0.f, 0.f, 0.f, 0.f);
                cur = g;
            }

            float s = f0.x * w0.x + f0.y * w0.y + f0.z * w0.z + f0.w * w0.w
                    + f1.x * w1.x + f1.y * w1.y + f1.z * w1.z + f1.w * w1.w;
            #pragma unroll
            for (int o = 16; o > 0; o >>= 1)
                s += __shfl_xor_sync(0xFFFFFFFFu, s, o);

            const float wgt = __fdividef(1.0f, 1.0f + __expf(-(s + bias)));

            a0.x += f0.x * wgt; a0.y += f0.y * wgt;
            a0.z += f0.z * wgt; a0.w += f0.w * wgt;
            a1.x += f1.x * wgt; a1.y += f1.y * wgt;
            a1.z += f1.z * wgt; a1.w += f1.w * wgt;
        }

        flush_seg(out, cur, num_segs, lane, a0, a1);
        cbase = nbase;
    }
}

extern "C" void kernel_launch(void* const* d_in, const int* in_sizes, int n_in,
                              void* d_out, int out_size) {
    const float* feat  = (const float*)d_in[0];  // [N, 256] f32
    const int*   batch = (const int*)d_in[1];    // [N] i32, sorted
    const float* W     = (const float*)d_in[2];  // [256, 1] f32
    const float* b     = (const float*)d_in[3];  // [1] f32
    float*       out   = (float*)d_out;          // [num_segs, 256] f32

    const int N        = in_sizes[1];
    const int num_segs = out_size / CHANNELS;    // 2048

    const int n4 = out_size / 4;
    hgp_zero_kernel<<<(n4 + THREADS - 1) / THREADS, THREADS>>>(
        (float4*)out, n4);

    // 148 SMs * 5 blocks * 8 warps = 5920 warps, interleaved 8-node chunks.
    const int blocks = 740;
    hgp_pool_kernel<<<blocks, THREADS>>>(feat, batch, W, b, out, N, num_segs);
}

// round 11
// speedup vs baseline: 1.9974x; 1.3833x over previous
#include <cuda_runtime.h>
#include <cuda_bf16.h>
#include <cstdint>

// ---------------------------------------------------------------------------
// HyperbolicGraphPooling: out[g] = sum_{n: batch[n]==g} sigmoid(f[n]·W+b) * f[n]
// N=500000, C=256, 2048 graphs, batch int32 sorted ascending.
// R11 = R7 (best: 87.1us, 6.08TB/s = ~96% of LTS cap; R8/R9/R10 proved the
// plateau) + PDL overlap of the zero kernel with the pool kernel's streaming
// ramp. Pool kernel defers griddepcontrol.wait until its FIRST atomic flush
// (tens of us in), so zeroing is fully hidden. Target ~84-85.5 us.
// ---------------------------------------------------------------------------

#define CHANNELS 256
#define THREADS  256
#define WARPS    (THREADS / 32)
#define STAGES   4

__global__ void hgp_zero_kernel(float4* __restrict__ out, int n4) {
    int i = blockIdx.x * blockDim.x + threadIdx.x;
    if (i < n4) out[i] = make_float4(0.f, 0.f, 0.f, 0.f);
    // Allow the dependent (pool) kernel to begin launching now.
    asm volatile("griddepcontrol.launch_dependents;" ::: "memory");
}

__device__ __forceinline__ void pdl_wait_once(bool& waited) {
    if (!waited) {
        // Block until the zero kernel's stores are globally visible.
        asm volatile("griddepcontrol.wait;" ::: "memory");
        waited = true;
    }
}

__device__ __forceinline__ void flush_seg(float* __restrict__ out,
                                          int seg, int num_segs, int lane,
                                          const float4& a0, const float4& a1) {
    if (seg < 0 || seg >= num_segs) return;   // defensive
    float* p0 = out + (size_t)seg * CHANNELS + 4 * lane;
    float* p1 = p0 + 128;
    atomicAdd(p0 + 0, a0.x);
    atomicAdd(p0 + 1, a0.y);
    atomicAdd(p0 + 2, a0.z);
    atomicAdd(p0 + 3, a0.w);
    atomicAdd(p1 + 0, a1.x);
    atomicAdd(p1 + 1, a1.y);
    atomicAdd(p1 + 2, a1.z);
    atomicAdd(p1 + 3, a1.w);
}

__device__ __forceinline__ void cp_row(unsigned int s_dst,
                                       const float* __restrict__ feat,
                                       int row, int lane) {
    // Each lane copies its own 32B: channels [4*lane,4*lane+4) and +128.
    const char* g = reinterpret_cast<const char*>(feat + (size_t)row * CHANNELS)
                    + lane * 16;
    asm volatile("cp.async.cg.shared.global [%0], [%1], 16;\n"
                 "cp.async.cg.shared.global [%2], [%3], 16;"
                 :: "r"(s_dst + lane * 16), "l"(g),
                    "r"(s_dst + 512 + lane * 16), "l"(g + 512));
}

__global__ __launch_bounds__(THREADS, 5)
void hgp_pool_kernel(const float* __restrict__ feat,
                     const int* __restrict__ batch,
                     const float* __restrict__ W,
                     const float* __restrict__ b,
                     float* __restrict__ out,
                     int N, int num_segs) {
    __shared__ __align__(16) float ring[WARPS][STAGES][CHANNELS];

    const int lane        = threadIdx.x & 31;
    const int wid         = threadIdx.x >> 5;
    const int warp_global = (blockIdx.x * blockDim.x + threadIdx.x) >> 5;
    const int total_warps = (gridDim.x * blockDim.x) >> 5;

    const int per = (N + total_warps - 1) / total_warps;
    const int n0  = warp_global * per;
    const int n1  = (n0 + per < N) ? (n0 + per) : N;
    if (n0 >= n1) return;

    const unsigned int s_base =
        (unsigned int)__cvta_generic_to_shared(&ring[wid][0][0]);

    const float4 w0 = *reinterpret_cast<const float4*>(W + 4 * lane);
    const float4 w1 = *reinterpret_cast<const float4*>(W + 128 + 4 * lane);
    const float bias = b[0];

    float4 a0 = make_float4(0.f, 0.f, 0.f, 0.f);
    float4 a1 = make_float4(0.f, 0.f, 0.f, 0.f);
    int cur = batch[n0];
    bool waited = false;   // PDL: wait for zero kernel before first flush

    // Prologue: issue rows n0 .. n0+STAGES-2, one commit group per row
    // (empty groups are legal and keep the count uniform).
    #pragma unroll
    for (int p = 0; p < STAGES - 1; ++p) {
        const int pn = n0 + p;
        if (pn < n1)
            cp_row(s_base + ((pn & (STAGES - 1)) << 10), feat, pn, lane);
        asm volatile("cp.async.commit_group;" ::: "memory");
    }

    for (int n = n0; n < n1; ++n) {
        // Issue row n+3 into its slot, commit (possibly empty near the end).
        const int pn = n + STAGES - 1;
        if (pn < n1)
            cp_row(s_base + ((pn & (STAGES - 1)) << 10), feat, pn, lane);
        asm volatile("cp.async.commit_group;" ::: "memory");

        const int g = __ldg(batch + n);

        // Row n's group is the 4th most recent => wait_group 3 suffices.
        asm volatile("cp.async.wait_group 3;" ::: "memory");

        // Each lane reads back exactly the 32B it wrote (no cross-lane smem,
        // so per-thread cp.async visibility suffices; no __syncwarp needed).
        const float* srow = &ring[wid][n & (STAGES - 1)][0];
        const float4 f0 = *reinterpret_cast<const float4*>(srow + 4 * lane);
        const float4 f1 = *reinterpret_cast<const float4*>(srow + 128 + 4 * lane);

        if (g != cur) {
            pdl_wait_once(waited);
            flush_seg(out, cur, num_segs, lane, a0, a1);
            a0 = make_float4(0.f, 0.f, 0.f, 0.f);
            a1 = make_float4(0.f, 0.f, 0.f, 0.f);
            cur = g;
        }

        float s = f0.x * w0.x + f0.y * w0.y + f0.z * w0.z + f0.w * w0.w
                + f1.x * w1.x + f1.y * w1.y + f1.z * w1.z + f1.w * w1.w;
        #pragma unroll
        for (int o = 16; o > 0; o >>= 1)
            s += __shfl_xor_sync(0xFFFFFFFFu, s, o);

        const float wgt = __fdividef(1.0f, 1.0f + __expf(-(s + bias)));

        a0.x += f0.x * wgt; a0.y += f0.y * wgt;
        a0.z += f0.z * wgt; a0.w += f0.w * wgt;
        a1.x += f1.x * wgt; a1.y += f1.y * wgt;
        a1.z += f1.z * wgt; a1.w += f1.w * wgt;
    }

    pdl_wait_once(waited);
    flush_seg(out, cur, num_segs, lane, a0, a1);
}

extern "C" void kernel_launch(void* const* d_in, const int* in_sizes, int n_in,
                              void* d_out, int out_size) {
    const float* feat  = (const float*)d_in[0];  // [N, 256] f32
    const int*   batch = (const int*)d_in[1];    // [N] i32, sorted
    const float* W     = (const float*)d_in[2];  // [256, 1] f32
    const float* b     = (const float*)d_in[3];  // [1] f32
    float*       out   = (float*)d_out;          // [num_segs, 256] f32

    const int N        = in_sizes[1];
    const int num_segs = out_size / CHANNELS;    // 2048

    // Zero output (harness poisons it before each timed replay).
    const int n4 = out_size / 4;
    hgp_zero_kernel<<<(n4 + THREADS - 1) / THREADS, THREADS>>>(
        (float4*)out, n4);

    // Pool kernel launched with PDL so it overlaps the zero kernel's tail;
    // it synchronizes via griddepcontrol.wait before its first flush.
    {
        cudaLaunchConfig_t cfg = {};
        cfg.gridDim  = dim3(740, 1, 1);   // 148 SMs * 5 blocks, one wave
        cfg.blockDim = dim3(THREADS, 1, 1);
        cfg.dynamicSmemBytes = 0;
        cfg.stream = 0;
        cudaLaunchAttribute attrs[1];
        attrs[0].id = cudaLaunchAttributeProgrammaticStreamSerialization;
        attrs[0].val.programmaticStreamSerializationAllowed = 1;
        cfg.attrs = attrs;
        cfg.numAttrs = 1;
        cudaLaunchKernelEx(&cfg, hgp_pool_kernel,
                           feat, batch, W, b, out, N, num_segs);
    }
}